// round 2
// baseline (speedup 1.0000x reference)
#include <cuda_runtime.h>

#define HH   48
#define HH2  (48*48)
#define HH3  (48*48*48)
#define NT   256
#define NEG_BIG (-3.402823466e38f)

// Shared workspace (one copy, shared by all template instantiations)
struct Smem {
    float sq[216], sk[216], sv[216];   // pooled q,k,v: [c*27 + token]
    float sc[27*28];                   // scores / weights, padded rows
    float so[216];                     // attention out: [c*27 + token]
    float bias[125];                   // rpb for this head
    float wgt[24];                     // interp fractional weight per out pos
    int   i0[24];                      // interp left index per out pos
};

template<int SW>
__device__ __forceinline__ void load_row_max(const float* __restrict__ p, float& m) {
    if (SW == 8) {
        float4 a = *(const float4*)p;
        float4 b = *(const float4*)(p + 4);
        m = fmaxf(m, fmaxf(fmaxf(fmaxf(a.x, a.y), fmaxf(a.z, a.w)),
                           fmaxf(fmaxf(b.x, b.y), fmaxf(b.z, b.w))));
    } else if (SW == 4) {
        float4 a = *(const float4*)p;
        m = fmaxf(m, fmaxf(fmaxf(a.x, a.y), fmaxf(a.z, a.w)));
    } else if (SW == 2) {
        float2 a = *(const float2*)p;
        m = fmaxf(m, fmaxf(a.x, a.y));
    } else {
        m = fmaxf(m, *p);
    }
}

template<int BW, int SW, int SCALE, int N1>
__device__ __forceinline__ void do_window(
    const float* __restrict__ q, const float* __restrict__ k,
    const float* __restrict__ v, const float* __restrict__ rpb,
    float* __restrict__ out, Smem& sm, int rem)
{
    const int tid = threadIdx.x;
    int wx = rem % N1; rem /= N1;
    int wy = rem % N1; rem /= N1;
    int wz = rem % N1; rem /= N1;
    int head = rem & 1;
    int b    = rem >> 1;
    const int chan_base = b*64 + (SCALE*2 + head)*8;

    // ---- small tables ----
    if (tid < 125) sm.bias[tid] = rpb[tid*2 + head];
    if (tid < BW) {
        float pos = (float)tid * (2.0f / (float)(BW - 1)); // align_corners interp, n_in=3
        int i0 = (pos >= 1.0f) ? 1 : 0;                    // floor clamped to [0,1]
        sm.i0[tid]  = i0;
        sm.wgt[tid] = pos - (float)i0;
    }

    // ---- phase 1: fused max-pool of q,k,v into (27 tokens x 8 ch) ----
    constexpr int G    = (SW == 8) ? 32 : (SW == 4) ? 8 : (SW == 2) ? 4 : 1;
    constexpr int ROWS = (SW * SW) / G;   // x-rows per thread (SW=1 -> 1)
    for (int u = tid; u < 216 * G; u += NT) {
        int p = u / G, g = u - p * G;
        int c  = p / 27, t  = p - c * 27;
        int nz = t / 9,  r2 = t - nz * 9;
        int ny = r2 / 3, nx = r2 - ny * 3;
        int zb = wz*BW + nz*SW;
        int yb = wy*BW + ny*SW;
        int xb = wx*BW + nx*SW;
        float mq = NEG_BIG, mk = NEG_BIG, mv = NEG_BIG;
        #pragma unroll
        for (int rr = 0; rr < ROWS; rr++) {
            int row = g * ROWS + rr;              // in [0, SW*SW)
            int dz = row / SW, dy = row - dz * SW;
            int off = (chan_base + c)*HH3 + (zb + dz)*HH2 + (yb + dy)*HH + xb;
            load_row_max<SW>(q + off, mq);
            load_row_max<SW>(k + off, mk);
            load_row_max<SW>(v + off, mv);
        }
        if (G > 1) {
            #pragma unroll
            for (int o = G >> 1; o > 0; o >>= 1) {
                mq = fmaxf(mq, __shfl_xor_sync(0xffffffffu, mq, o));
                mk = fmaxf(mk, __shfl_xor_sync(0xffffffffu, mk, o));
                mv = fmaxf(mv, __shfl_xor_sync(0xffffffffu, mv, o));
            }
        }
        if (g == 0) { sm.sq[p] = mq; sm.sk[p] = mk; sm.sv[p] = mv; }
    }
    __syncthreads();

    // ---- phase 2: scores = q k^T / sqrt(8) ----
    for (int j = tid; j < 729; j += NT) {
        int m = j / 27, n = j - m * 27;
        float s = 0.f;
        #pragma unroll
        for (int c = 0; c < 8; c++) s += sm.sq[c*27 + m] * sm.sk[c*27 + n];
        sm.sc[m*28 + n] = s * 0.35355339059327373f;
    }
    __syncthreads();

    // ---- phase 3: softmax per row, then ADD bias (post-softmax, per reference) ----
    {
        int wid = tid >> 5, lane = tid & 31;
        for (int m = wid; m < 27; m += NT/32) {
            float x = (lane < 27) ? sm.sc[m*28 + lane] : NEG_BIG;
            float mx = x;
            #pragma unroll
            for (int o = 16; o > 0; o >>= 1) mx = fmaxf(mx, __shfl_xor_sync(0xffffffffu, mx, o));
            float e = (lane < 27) ? __expf(x - mx) : 0.f;
            float s = e;
            #pragma unroll
            for (int o = 16; o > 0; o >>= 1) s += __shfl_xor_sync(0xffffffffu, s, o);
            if (lane < 27) {
                int mz = m / 9,   mr = m - mz*9,   my = mr / 3,  mxc = mr - my*3;
                int nz = lane / 9, nr = lane - nz*9, ny2 = nr / 3, nx2 = nr - ny2*3;
                int bidx = (mz - nz + 2)*25 + (my - ny2 + 2)*5 + (mxc - nx2 + 2);
                sm.sc[m*28 + lane] = e / s + sm.bias[bidx];
            }
        }
    }
    __syncthreads();

    // ---- phase 4: out = w @ v ----
    for (int p = tid; p < 216; p += NT) {
        int c = p / 27, m = p - c * 27;
        float acc = 0.f;
        #pragma unroll
        for (int n = 0; n < 27; n++) acc += sm.sc[m*28 + n] * sm.sv[c*27 + n];
        sm.so[p] = acc;
    }
    __syncthreads();

    // ---- phase 5: trilinear upsample 3^3 -> BW^3 and scatter ----
    constexpr int VEC = (BW % 4 == 0) ? 4 : (BW % 2 == 0) ? 2 : 1;
    constexpr int RX  = BW / VEC;
    for (int u = tid; u < 8*BW*BW*RX; u += NT) {
        int rv   = u % RX;  int rest = u / RX;
        int qq   = rest % BW; rest /= BW;
        int pp   = rest % BW; int c = rest / BW;
        int ip = sm.i0[pp]; float wp = sm.wgt[pp];
        int iq = sm.i0[qq]; float wq = sm.wgt[qq];
        const float* soc = &sm.so[c*27];
        // interpolate over z(pp), y(qq) for the 3 x positions
        float w00 = (1.f - wp) * (1.f - wq);
        float w01 = (1.f - wp) * wq;
        float w10 = wp * (1.f - wq);
        float w11 = wp * wq;
        int b00 = ip*9 + iq*3;
        int b01 = ip*9 + (iq+1)*3;
        int b10 = (ip+1)*9 + iq*3;
        int b11 = (ip+1)*9 + (iq+1)*3;
        float t0 = w00*soc[b00+0] + w01*soc[b01+0] + w10*soc[b10+0] + w11*soc[b11+0];
        float t1 = w00*soc[b00+1] + w01*soc[b01+1] + w10*soc[b10+1] + w11*soc[b11+1];
        float t2 = w00*soc[b00+2] + w01*soc[b01+2] + w10*soc[b10+2] + w11*soc[b11+2];
        float res[4];
        #pragma unroll
        for (int e = 0; e < VEC; e++) {
            int r = rv*VEC + e;
            int ir = sm.i0[r]; float wr = sm.wgt[r];
            float a0 = (ir == 0) ? t0 : t1;
            float a1 = (ir == 0) ? t1 : t2;
            res[e] = (1.f - wr) * a0 + wr * a1;
        }
        int z = wz*BW + pp, y = wy*BW + qq, x = wx*BW + rv*VEC;
        int oidx = (chan_base + c)*HH3 + z*HH2 + y*HH + x;
        if (VEC == 4)      *(float4*)(out + oidx) = make_float4(res[0], res[1], res[2], res[3]);
        else if (VEC == 2) *(float2*)(out + oidx) = make_float2(res[0], res[1]);
        else               out[oidx] = res[0];
    }
}

// Block ranges (heavy scale first so the 64 bw=24 CTAs overlap the whole kernel):
//   [0,64)      scale 3: bw=24 sw=8  N1=2
//   [64,576)    scale 2: bw=12 sw=4  N1=4
//   [576,4672)  scale 1: bw=6  sw=2  N1=8
//   [4672,37440) scale 0: bw=3 sw=1  N1=16
__global__ void __launch_bounds__(NT)
pwa_kernel(const float* __restrict__ q, const float* __restrict__ k,
           const float* __restrict__ v, const float* __restrict__ rpb,
           float* __restrict__ out)
{
    __shared__ Smem sm;
    int bid = blockIdx.x;
    if (bid < 64)        do_window<24, 8, 3, 2 >(q, k, v, rpb, out, sm, bid);
    else if (bid < 576)  do_window<12, 4, 2, 4 >(q, k, v, rpb, out, sm, bid - 64);
    else if (bid < 4672) do_window< 6, 2, 1, 8 >(q, k, v, rpb, out, sm, bid - 576);
    else                 do_window< 3, 1, 0, 16>(q, k, v, rpb, out, sm, bid - 4672);
}

extern "C" void kernel_launch(void* const* d_in, const int* in_sizes, int n_in,
                              void* d_out, int out_size)
{
    const float* q   = (const float*)d_in[0];
    const float* k   = (const float*)d_in[1];
    const float* v   = (const float*)d_in[2];
    const float* rpb = (const float*)d_in[3];
    pwa_kernel<<<37440, NT>>>(q, k, v, rpb, (float*)d_out);
}

// round 3
// speedup vs baseline: 1.8805x; 1.8805x over previous
#include <cuda_runtime.h>

#define HH   48
#define HH2  2304
#define HH3  110592
#define NT   512
#define NEG_BIG (-3.402823466e38f)

__device__ __forceinline__ float4 fmax4(float4 a, float4 b) {
    return make_float4(fmaxf(a.x,b.x), fmaxf(a.y,b.y), fmaxf(a.z,b.z), fmaxf(a.w,b.w));
}
__device__ __forceinline__ float hmax4(float4 a) {
    return fmaxf(fmaxf(a.x,a.y), fmaxf(a.z,a.w));
}

// CTA covers (b, head, wz, wy) and all NW windows along x.
// Pooled layout (A=q, B=k, C=v): [((pz*3+py)*X + px)*8 + c], X = 3*NW.
// After attention, A is reused for "so" in c-major layout: [c*9X + (pz*3+py)*X + px].
template<int BW, int SW, int NW, int SCALE>
__device__ __forceinline__ void do_scale(
    const float* __restrict__ q, const float* __restrict__ k,
    const float* __restrict__ v, const float* __restrict__ rpb,
    float* __restrict__ out, float* sm, int rem)
{
    constexpr int X = 3*NW;
    constexpr int P = 72*X;
    const int tid = threadIdx.x;
    int wy = rem % NW; rem /= NW;
    int wz = rem % NW; rem /= NW;
    int head = rem & 1;
    int b    = rem >> 1;
    const int cb = (b*64 + (SCALE*2+head)*8) * HH3;

    float* bias27 = sm;          // 27*29 padded
    float* A  = sm + 800;
    float* Bm = A + P;
    float* Cm = Bm + P;
    float* sZ = Cm + P;          // 3456 (z-interp) or 2*3456 (SW=8 staging)

    // ---- expanded bias table ----
    for (int u = tid; u < 729; u += NT) {
        int m = u / 27, n = u - m*27;
        int d0 = m/9 - n/9 + 2;
        int d1 = (m/3)%3 - (n/3)%3 + 2;
        int d2 = m%3 - n%3 + 2;
        bias27[m*29+n] = rpb[(d0*25 + d1*5 + d2)*2 + head];
    }

    // ---- pooling (all loads row-contiguous float4) ----
    if (SW == 1) {
        for (int u = tid; u < 864; u += NT) {
            int xg = u % 12; int t = u / 12; int c = t & 7; t >>= 3; int py = t % 3; int pz = t / 3;
            int g = cb + c*HH3 + (wz*3+pz)*HH2 + (wy*3+py)*HH + xg*4;
            float4 aq = *(const float4*)(q+g);
            float4 ak = *(const float4*)(k+g);
            float4 av = *(const float4*)(v+g);
            int tok = ((pz*3+py)*48 + xg*4)*8 + c;
            A [tok] = aq.x; A [tok+8] = aq.y; A [tok+16] = aq.z; A [tok+24] = aq.w;
            Bm[tok] = ak.x; Bm[tok+8] = ak.y; Bm[tok+16] = ak.z; Bm[tok+24] = ak.w;
            Cm[tok] = av.x; Cm[tok+8] = av.y; Cm[tok+16] = av.z; Cm[tok+24] = av.w;
        }
    } else if (SW == 2) {
        for (int u = tid; u < 864; u += NT) {
            int xg = u % 12; int t = u / 12; int c = t & 7; t >>= 3; int py = t % 3; int pz = t / 3;
            int z0 = wz*6 + pz*2, y0 = wy*6 + py*2;
            float4 mq = make_float4(NEG_BIG,NEG_BIG,NEG_BIG,NEG_BIG), mk = mq, mv = mq;
            #pragma unroll
            for (int dz = 0; dz < 2; dz++)
            #pragma unroll
            for (int dy = 0; dy < 2; dy++) {
                int g = cb + c*HH3 + (z0+dz)*HH2 + (y0+dy)*HH + xg*4;
                mq = fmax4(mq, *(const float4*)(q+g));
                mk = fmax4(mk, *(const float4*)(k+g));
                mv = fmax4(mv, *(const float4*)(v+g));
            }
            int tok = ((pz*3+py)*24 + xg*2)*8 + c;
            A [tok] = fmaxf(mq.x,mq.y); A [tok+8] = fmaxf(mq.z,mq.w);
            Bm[tok] = fmaxf(mk.x,mk.y); Bm[tok+8] = fmaxf(mk.z,mk.w);
            Cm[tok] = fmaxf(mv.x,mv.y); Cm[tok+8] = fmaxf(mv.z,mv.w);
        }
    } else if (SW == 4) {
        for (int u = tid; u < 864; u += NT) {
            int px = u % 12; int t = u / 12; int c = t & 7; t >>= 3; int py = t % 3; int pz = t / 3;
            int z0 = wz*12 + pz*4, y0 = wy*12 + py*4;
            float4 mq = make_float4(NEG_BIG,NEG_BIG,NEG_BIG,NEG_BIG), mk = mq, mv = mq;
            #pragma unroll
            for (int dz = 0; dz < 4; dz++)
            #pragma unroll
            for (int dy = 0; dy < 4; dy++) {
                int g = cb + c*HH3 + (z0+dz)*HH2 + (y0+dy)*HH + px*4;
                mq = fmax4(mq, *(const float4*)(q+g));
                mk = fmax4(mk, *(const float4*)(k+g));
                mv = fmax4(mv, *(const float4*)(v+g));
            }
            int tok = ((pz*3+py)*12 + px)*8 + c;
            A[tok] = hmax4(mq); Bm[tok] = hmax4(mk); Cm[tok] = hmax4(mv);
        }
    } else { // SW == 8: stage1 pools x,y (coalesced), stage2 pools z
        float* sA0 = sZ; float* sA1 = sZ + 3456;
        for (int u = tid; u < 6912; u += NT) {
            int xg = u % 12; int t = u / 12; int c = t & 7; t >>= 3; int py = t % 3; int z = t / 3;
            int g = cb + c*HH3 + (wz*24+z)*HH2 + (wy*24+py*8)*HH + xg*4;
            float4 mq = *(const float4*)(q+g);
            float4 mk = *(const float4*)(k+g);
            #pragma unroll
            for (int dy = 1; dy < 8; dy++) {
                mq = fmax4(mq, *(const float4*)(q+g+dy*HH));
                mk = fmax4(mk, *(const float4*)(k+g+dy*HH));
            }
            float rq = hmax4(mq), rk = hmax4(mk);
            rq = fmaxf(rq, __shfl_xor_sync(0xffffffffu, rq, 1));
            rk = fmaxf(rk, __shfl_xor_sync(0xffffffffu, rk, 1));
            if (!(xg & 1)) {
                int s = ((z*3+py)*6 + (xg>>1))*8 + c;
                sA0[s] = rq; sA1[s] = rk;
            }
        }
        __syncthreads();
        for (int u = tid; u < 432; u += NT) {
            int c = u & 7; int t = u >> 3; int px = t % 6; t /= 6; int py = t % 3; int pz = t / 3;
            float rq = NEG_BIG, rk = NEG_BIG;
            #pragma unroll
            for (int j = 0; j < 8; j++) {
                int s = (((pz*8+j)*3+py)*6 + px)*8 + c;
                rq = fmaxf(rq, sA0[s]); rk = fmaxf(rk, sA1[s]);
            }
            int d = ((pz*3+py)*6 + px)*8 + c;
            A[d] = rq; Bm[d] = rk;
        }
        __syncthreads();
        for (int u = tid; u < 6912; u += NT) {
            int xg = u % 12; int t = u / 12; int c = t & 7; t >>= 3; int py = t % 3; int z = t / 3;
            int g = cb + c*HH3 + (wz*24+z)*HH2 + (wy*24+py*8)*HH + xg*4;
            float4 mv = *(const float4*)(v+g);
            #pragma unroll
            for (int dy = 1; dy < 8; dy++) mv = fmax4(mv, *(const float4*)(v+g+dy*HH));
            float rv = hmax4(mv);
            rv = fmaxf(rv, __shfl_xor_sync(0xffffffffu, rv, 1));
            if (!(xg & 1)) sA0[((z*3+py)*6 + (xg>>1))*8 + c] = rv;
        }
        __syncthreads();
        for (int u = tid; u < 432; u += NT) {
            int c = u & 7; int t = u >> 3; int px = t % 6; t /= 6; int py = t % 3; int pz = t / 3;
            float rv = NEG_BIG;
            #pragma unroll
            for (int j = 0; j < 8; j++) rv = fmaxf(rv, sA0[(((pz*8+j)*3+py)*6 + px)*8 + c]);
            Cm[((pz*3+py)*6 + px)*8 + c] = rv;
        }
    }
    __syncthreads();

    // ---- attention: warp wid = window, lane = token m; weights in registers ----
    const int wid = tid >> 5, lane = tid & 31;
    float w27[27];
    int mbase = 0;
    const bool act = (wid < NW) && (lane < 27);
    if (act) {
        int mz = lane/9, my = (lane/3)%3, mx = lane%3;
        mbase = (mz*3+my)*X + wid*3 + mx;
        const float4 q0 = *(const float4*)(A + mbase*8);
        const float4 q1 = *(const float4*)(A + mbase*8 + 4);
        float smax = NEG_BIG;
        #pragma unroll
        for (int n = 0; n < 27; n++) {
            int ntok = (((n/9)*3 + (n/3)%3)*X + wid*3 + n%3)*8;
            float4 k0 = *(const float4*)(Bm+ntok);
            float4 k1 = *(const float4*)(Bm+ntok+4);
            float s = q0.x*k0.x + q0.y*k0.y + q0.z*k0.z + q0.w*k0.w
                    + q1.x*k1.x + q1.y*k1.y + q1.z*k1.z + q1.w*k1.w;
            s *= 0.35355339059327373f;
            w27[n] = s;
            smax = fmaxf(smax, s);
        }
        float ssum = 0.f;
        #pragma unroll
        for (int n = 0; n < 27; n++) { float e = __expf(w27[n]-smax); w27[n] = e; ssum += e; }
        float rs = 1.f/ssum;
        #pragma unroll
        for (int n = 0; n < 27; n++) w27[n] = w27[n]*rs + bias27[lane*29+n];
    }
    __syncthreads();   // all reads of A (q) done before so overwrites A
    if (act) {
        float o0=0,o1=0,o2=0,o3=0,o4=0,o5=0,o6=0,o7=0;
        #pragma unroll
        for (int n = 0; n < 27; n++) {
            int ntok = (((n/9)*3 + (n/3)%3)*X + wid*3 + n%3)*8;
            float4 v0 = *(const float4*)(Cm+ntok);
            float4 v1 = *(const float4*)(Cm+ntok+4);
            float wn = w27[n];
            o0 += wn*v0.x; o1 += wn*v0.y; o2 += wn*v0.z; o3 += wn*v0.w;
            o4 += wn*v1.x; o5 += wn*v1.y; o6 += wn*v1.z; o7 += wn*v1.w;
        }
        A[0*9*X+mbase]=o0; A[1*9*X+mbase]=o1; A[2*9*X+mbase]=o2; A[3*9*X+mbase]=o3;
        A[4*9*X+mbase]=o4; A[5*9*X+mbase]=o5; A[6*9*X+mbase]=o6; A[7*9*X+mbase]=o7;
    }
    __syncthreads();

    // ---- scatter ----
    if (SCALE == 0) {
        for (int u = tid; u < 864; u += NT) {
            int xg = u % 12; int t = u / 12; int py = t % 3; t /= 3; int pz = t % 3; int c = t / 3;
            float4 val = *(const float4*)(A + c*432 + (pz*3+py)*48 + xg*4);
            int g = cb + c*HH3 + (wz*3+pz)*HH2 + (wy*3+py)*HH + xg*4;
            *(float4*)(out+g) = val;
        }
    } else {
        // z-interp: sZ[((c*BW+oz)*3+py)*X + px]
        for (int u = tid; u < 3456; u += NT) {   // 8*BW*3*X == 3456 for all scales
            int px = u % X; int t = u / X; int py = t % 3; t /= 3; int oz = t % BW; int c = t / BW;
            int iz = (2*oz >= BW-1) ? 1 : 0;
            float wzf = (float)(oz*2) / (float)(BW-1) - (float)iz;
            float a0 = A[c*9*X + (iz*3+py)*X + px];
            float a1 = A[c*9*X + ((iz+1)*3+py)*X + px];
            sZ[((c*BW+oz)*3+py)*X + px] = a0 + wzf*(a1-a0);
        }
        __syncthreads();
        constexpr int VEC = (BW == 6) ? 2 : 4;
        constexpr int NXG = 48/VEC;
        constexpr int ITEMS = 8*BW*BW*NXG;
        for (int u = tid; u < ITEMS; u += NT) {
            int xg = u % NXG; int t = u / NXG; int oy = t % BW; t /= BW; int oz = t % BW; int c = t / BW;
            int x0 = xg*VEC;
            int win = x0 / BW; int lx0 = x0 - win*BW;
            int iy = (2*oy >= BW-1) ? 1 : 0;
            float wyf = (float)(oy*2) / (float)(BW-1) - (float)iy;
            const float* z0 = sZ + ((c*BW+oz)*3+iy)*X + win*3;
            const float* z1 = z0 + X;
            float b0 = z0[0] + wyf*(z1[0]-z0[0]);
            float b1 = z0[1] + wyf*(z1[1]-z0[1]);
            float b2 = z0[2] + wyf*(z1[2]-z0[2]);
            float res[VEC];
            #pragma unroll
            for (int e = 0; e < VEC; e++) {
                int lx = lx0 + e;
                int il = (2*lx >= BW-1) ? 1 : 0;
                float wl = (float)(lx*2) / (float)(BW-1) - (float)il;
                float lo = il ? b1 : b0;
                float hi = il ? b2 : b1;
                res[e] = lo + wl*(hi-lo);
            }
            int g = cb + c*HH3 + (wz*BW+oz)*HH2 + (wy*BW+oy)*HH + x0;
            if (VEC == 4) *(float4*)(out+g) = make_float4(res[0],res[1],res[2],res[3]);
            else          *(float2*)(out+g) = make_float2(res[0],res[1]);
        }
    }
}

// Grid (heavy scales first):
//   [0,32)      scale 3: bw=24 sw=8  NW=2
//   [32,160)    scale 2: bw=12 sw=4  NW=4
//   [160,672)   scale 1: bw=6  sw=2  NW=8
//   [672,2720)  scale 0: bw=3  sw=1  NW=16
__global__ void __launch_bounds__(NT)
pwa_kernel(const float* __restrict__ q, const float* __restrict__ k,
           const float* __restrict__ v, const float* __restrict__ rpb,
           float* __restrict__ out)
{
    __shared__ float sm[11168];
    int bid = blockIdx.x;
    if (bid < 32)        do_scale<24, 8, 2,  3>(q, k, v, rpb, out, sm, bid);
    else if (bid < 160)  do_scale<12, 4, 4,  2>(q, k, v, rpb, out, sm, bid - 32);
    else if (bid < 672)  do_scale< 6, 2, 8,  1>(q, k, v, rpb, out, sm, bid - 160);
    else                 do_scale< 3, 1, 16, 0>(q, k, v, rpb, out, sm, bid - 672);
}

extern "C" void kernel_launch(void* const* d_in, const int* in_sizes, int n_in,
                              void* d_out, int out_size)
{
    const float* q   = (const float*)d_in[0];
    const float* k   = (const float*)d_in[1];
    const float* v   = (const float*)d_in[2];
    const float* rpb = (const float*)d_in[3];
    pwa_kernel<<<2720, NT>>>(q, k, v, rpb, (float*)d_out);
}